// round 1
// baseline (speedup 1.0000x reference)
#include <cuda_runtime.h>
#include <math.h>

#define BATCH 2
#define SEQ   2048
#define DIM   1024
#define HEADS 16
#define HDIM  64
#define MROWS (BATCH * SEQ)     /* 4096 */
#define NQKV  (3 * DIM)         /* 3072 */

// Scratch (device globals: no runtime allocation allowed)
__device__ float g_qkv[(size_t)MROWS * NQKV];   // ~50 MB
__device__ float g_att[(size_t)MROWS * DIM];    // ~17 MB

// ---------------------------------------------------------------------------
// SGEMM: C[M,N] = A[M,K] @ W[K,N] + bias[N]
// Block tile 128x128, K-chunk 8, 256 threads, 8x8 per thread.
// Requires M%128==0, N%128==0, K%8==0 (true for all our shapes).
// ---------------------------------------------------------------------------
__global__ __launch_bounds__(256) void gemm_bias_kernel(
    const float* __restrict__ A, const float* __restrict__ W,
    const float* __restrict__ bias, float* __restrict__ C,
    int M, int N, int K)
{
    __shared__ float As[8][128];   // transposed A tile: As[k][m]
    __shared__ float Bs[8][128];

    const int tid = threadIdx.x;
    const int n0 = blockIdx.x * 128;
    const int m0 = blockIdx.y * 128;

    const int arow = tid >> 1;          // 0..127
    const int acol = (tid & 1) * 4;     // 0 or 4
    const int brow = tid >> 5;          // 0..7
    const int bcol = (tid & 31) * 4;    // 0..124

    const int tx = tid & 15;            // col group
    const int ty = tid >> 4;            // row group

    float acc[8][8];
#pragma unroll
    for (int i = 0; i < 8; ++i)
#pragma unroll
        for (int j = 0; j < 8; ++j) acc[i][j] = 0.f;

    for (int k0 = 0; k0 < K; k0 += 8) {
        float4 av = *(const float4*)(A + (size_t)(m0 + arow) * K + k0 + acol);
        float4 bv = *(const float4*)(W + (size_t)(k0 + brow) * N + n0 + bcol);
        __syncthreads();
        As[acol + 0][arow] = av.x;
        As[acol + 1][arow] = av.y;
        As[acol + 2][arow] = av.z;
        As[acol + 3][arow] = av.w;
        *(float4*)&Bs[brow][bcol] = bv;
        __syncthreads();
#pragma unroll
        for (int k = 0; k < 8; ++k) {
            float a[8], b[8];
            *(float4*)(a)     = *(const float4*)&As[k][ty * 8];
            *(float4*)(a + 4) = *(const float4*)&As[k][ty * 8 + 4];
            *(float4*)(b)     = *(const float4*)&Bs[k][tx * 8];
            *(float4*)(b + 4) = *(const float4*)&Bs[k][tx * 8 + 4];
#pragma unroll
            for (int i = 0; i < 8; ++i)
#pragma unroll
                for (int j = 0; j < 8; ++j)
                    acc[i][j] += a[i] * b[j];
        }
    }

    float4 bias0 = *(const float4*)(bias + n0 + tx * 8);
    float4 bias1 = *(const float4*)(bias + n0 + tx * 8 + 4);
#pragma unroll
    for (int i = 0; i < 8; ++i) {
        const int row = m0 + ty * 8 + i;
        float4 c0, c1;
        c0.x = acc[i][0] + bias0.x; c0.y = acc[i][1] + bias0.y;
        c0.z = acc[i][2] + bias0.z; c0.w = acc[i][3] + bias0.w;
        c1.x = acc[i][4] + bias1.x; c1.y = acc[i][5] + bias1.y;
        c1.z = acc[i][6] + bias1.z; c1.w = acc[i][7] + bias1.w;
        float4* cp = (float4*)(C + (size_t)row * N + n0 + tx * 8);
        cp[0] = c0;
        cp[1] = c1;
    }
}

// ---------------------------------------------------------------------------
// Flash attention (causal), fp32.
// Grid: (S/64, B*H). 256 threads (16x16), 64-query tile per block.
// qkv layout: [B*S, 3*DIM]; q at col h*64, k at DIM + h*64, v at 2*DIM + h*64.
// Online softmax matches ref: logits masked to -inf, valid logits * (1/8).
// ---------------------------------------------------------------------------
#define KS_STRIDE 65

__global__ __launch_bounds__(256) void flash_attn_kernel(
    const float* __restrict__ qkv, float* __restrict__ out)
{
    extern __shared__ float smem[];
    float* Qs = smem;                 // 64*64
    float* Vs = Qs + 64 * 64;         // 64*64
    float* Ps = Vs + 64 * 64;         // 64*64
    float* Ks = Ps + 64 * 64;         // 64*65 (padded, natural [kv][d] layout)

    const int tid = threadIdx.x;
    const int tx = tid & 15;
    const int ty = tid >> 4;

    const int bh = blockIdx.y;
    const int b = bh / HEADS;
    const int h = bh % HEADS;
    const int qt = gridDim.x - 1 - blockIdx.x;   // heavy tiles first
    const int q0 = qt * 64;
    const float scale = 0.125f;                   // 1/sqrt(64)

    const float* qbase = qkv + (size_t)(b * SEQ) * NQKV + h * HDIM;
    const float* kbase = qbase + DIM;
    const float* vbase = qbase + 2 * DIM;

    // Load Q tile (64 rows x 64 cols), coalesced float4
    {
        const int r = tid >> 4;
        const int c = (tid & 15) * 4;
#pragma unroll
        for (int rr = 0; rr < 64; rr += 16) {
            float4 v = *(const float4*)(qbase + (size_t)(q0 + r + rr) * NQKV + c);
            *(float4*)&Qs[(r + rr) * 64 + c] = v;
        }
    }

    float m_i[4], l_i[4], o[4][4];
#pragma unroll
    for (int i = 0; i < 4; ++i) {
        m_i[i] = -INFINITY;
        l_i[i] = 0.f;
#pragma unroll
        for (int j = 0; j < 4; ++j) o[i][j] = 0.f;
    }

    const int ntiles = qt + 1;
    for (int t = 0; t < ntiles; ++t) {
        const int k0 = t * 64;
        __syncthreads();  // protect Ks/Vs/Ps reuse (and Q load on iter 0)
        {
            const int r = tid >> 4;
            const int c = (tid & 15) * 4;
#pragma unroll
            for (int rr = 0; rr < 64; rr += 16) {
                float4 kv = *(const float4*)(kbase + (size_t)(k0 + r + rr) * NQKV + c);
                Ks[(r + rr) * KS_STRIDE + c + 0] = kv.x;
                Ks[(r + rr) * KS_STRIDE + c + 1] = kv.y;
                Ks[(r + rr) * KS_STRIDE + c + 2] = kv.z;
                Ks[(r + rr) * KS_STRIDE + c + 3] = kv.w;
                float4 vv = *(const float4*)(vbase + (size_t)(k0 + r + rr) * NQKV + c);
                *(float4*)&Vs[(r + rr) * 64 + c] = vv;
            }
        }
        __syncthreads();

        // S tile: s[i][j] = Q[q0+ty*4+i] . K[k0+tx*4+j]
        float s[4][4];
#pragma unroll
        for (int i = 0; i < 4; ++i)
#pragma unroll
            for (int j = 0; j < 4; ++j) s[i][j] = 0.f;

#pragma unroll 4
        for (int k = 0; k < 64; ++k) {
            float a0 = Qs[(ty * 4 + 0) * 64 + k];
            float a1 = Qs[(ty * 4 + 1) * 64 + k];
            float a2 = Qs[(ty * 4 + 2) * 64 + k];
            float a3 = Qs[(ty * 4 + 3) * 64 + k];
            float b0 = Ks[(tx * 4 + 0) * KS_STRIDE + k];
            float b1 = Ks[(tx * 4 + 1) * KS_STRIDE + k];
            float b2 = Ks[(tx * 4 + 2) * KS_STRIDE + k];
            float b3 = Ks[(tx * 4 + 3) * KS_STRIDE + k];
            s[0][0] += a0 * b0; s[0][1] += a0 * b1; s[0][2] += a0 * b2; s[0][3] += a0 * b3;
            s[1][0] += a1 * b0; s[1][1] += a1 * b1; s[1][2] += a1 * b2; s[1][3] += a1 * b3;
            s[2][0] += a2 * b0; s[2][1] += a2 * b1; s[2][2] += a2 * b2; s[2][3] += a2 * b3;
            s[3][0] += a3 * b0; s[3][1] += a3 * b1; s[3][2] += a3 * b2; s[3][3] += a3 * b3;
        }

        const bool diag = (t == ntiles - 1);
#pragma unroll
        for (int i = 0; i < 4; ++i) {
            const int qi = q0 + ty * 4 + i;
#pragma unroll
            for (int j = 0; j < 4; ++j) {
                const int kj = k0 + tx * 4 + j;
                float v = s[i][j] * scale;
                if (diag && kj > qi) v = -INFINITY;
                s[i][j] = v;
            }
        }

        // Online softmax update
#pragma unroll
        for (int i = 0; i < 4; ++i) {
            float tm = fmaxf(fmaxf(s[i][0], s[i][1]), fmaxf(s[i][2], s[i][3]));
#pragma unroll
            for (int off = 8; off >= 1; off >>= 1)
                tm = fmaxf(tm, __shfl_xor_sync(0xffffffffu, tm, off));
            const float newm = fmaxf(m_i[i], tm);
            const float corr = __expf(m_i[i] - newm);   // exp(-inf)=0 on first tile
            float rs = 0.f;
#pragma unroll
            for (int j = 0; j < 4; ++j) {
                const float p = __expf(s[i][j] - newm);
                s[i][j] = p;
                rs += p;
            }
#pragma unroll
            for (int off = 8; off >= 1; off >>= 1)
                rs += __shfl_xor_sync(0xffffffffu, rs, off);
            l_i[i] = l_i[i] * corr + rs;
#pragma unroll
            for (int j = 0; j < 4; ++j) o[i][j] *= corr;
            m_i[i] = newm;
        }

        // Stash P, then O += P @ V
#pragma unroll
        for (int i = 0; i < 4; ++i)
#pragma unroll
            for (int j = 0; j < 4; ++j)
                Ps[(ty * 4 + i) * 64 + tx * 4 + j] = s[i][j];
        __syncthreads();

#pragma unroll 4
        for (int k = 0; k < 64; ++k) {
            const float4 vb = *(const float4*)&Vs[k * 64 + tx * 4];
            float p0 = Ps[(ty * 4 + 0) * 64 + k];
            float p1 = Ps[(ty * 4 + 1) * 64 + k];
            float p2 = Ps[(ty * 4 + 2) * 64 + k];
            float p3 = Ps[(ty * 4 + 3) * 64 + k];
            o[0][0] += p0 * vb.x; o[0][1] += p0 * vb.y; o[0][2] += p0 * vb.z; o[0][3] += p0 * vb.w;
            o[1][0] += p1 * vb.x; o[1][1] += p1 * vb.y; o[1][2] += p1 * vb.z; o[1][3] += p1 * vb.w;
            o[2][0] += p2 * vb.x; o[2][1] += p2 * vb.y; o[2][2] += p2 * vb.z; o[2][3] += p2 * vb.w;
            o[3][0] += p3 * vb.x; o[3][1] += p3 * vb.y; o[3][2] += p3 * vb.z; o[3][3] += p3 * vb.w;
        }
    }

    // Write normalized output tile
#pragma unroll
    for (int i = 0; i < 4; ++i) {
        const int row = q0 + ty * 4 + i;
        const float inv = 1.0f / l_i[i];
        float4 v;
        v.x = o[i][0] * inv; v.y = o[i][1] * inv;
        v.z = o[i][2] * inv; v.w = o[i][3] * inv;
        *(float4*)(out + ((size_t)(b * SEQ) + row) * DIM + h * HDIM + tx * 4) = v;
    }
}

// ---------------------------------------------------------------------------
extern "C" void kernel_launch(void* const* d_in, const int* in_sizes, int n_in,
                              void* d_out, int out_size)
{
    const float* x      = (const float*)d_in[0];   // [B,S,D]
    const float* qkv_w  = (const float*)d_in[1];   // [D, 3D]
    const float* qkv_b  = (const float*)d_in[2];   // [3D]
    const float* out_w  = (const float*)d_in[3];   // [D, D]
    const float* out_b  = (const float*)d_in[4];   // [D]
    float* out = (float*)d_out;

    float* qkv_buf = nullptr;
    float* att_buf = nullptr;
    cudaGetSymbolAddress((void**)&qkv_buf, g_qkv);
    cudaGetSymbolAddress((void**)&att_buf, g_att);

    const int smem_bytes = (3 * 64 * 64 + 64 * KS_STRIDE) * (int)sizeof(float); // 65792
    cudaFuncSetAttribute(flash_attn_kernel,
                         cudaFuncAttributeMaxDynamicSharedMemorySize, smem_bytes);

    // 1) QKV projection: [4096,1024] @ [1024,3072] + b
    {
        dim3 grid(NQKV / 128, MROWS / 128);
        gemm_bias_kernel<<<grid, 256>>>(x, qkv_w, qkv_b, qkv_buf,
                                        MROWS, NQKV, DIM);
    }
    // 2) Causal flash attention
    {
        dim3 grid(SEQ / 64, BATCH * HEADS);
        flash_attn_kernel<<<grid, 256, smem_bytes>>>(qkv_buf, att_buf);
    }
    // 3) Output projection: [4096,1024] @ [1024,1024] + b
    {
        dim3 grid(DIM / 128, MROWS / 128);
        gemm_bias_kernel<<<grid, 256>>>(att_buf, out_w, out_b, out,
                                        MROWS, DIM, DIM);
    }
}

// round 2
// speedup vs baseline: 2.8613x; 2.8613x over previous
#include <cuda_runtime.h>
#include <math.h>

#define BATCH 2
#define SEQ   2048
#define DIM   1024
#define HEADS 16
#define HDIM  64
#define MROWS (BATCH * SEQ)     /* 4096 */
#define NQKV  (3 * DIM)         /* 3072 */

// Scratch (device globals: no runtime allocation allowed)
__device__ float g_qkv[(size_t)MROWS * NQKV];   // ~50 MB
__device__ float g_att[(size_t)MROWS * DIM];    // ~17 MB

// ---------------------------------------------------------------------------
// tf32 helpers
// ---------------------------------------------------------------------------
__device__ __forceinline__ float tf32r(float x) {
    unsigned u;
    asm("cvt.rna.tf32.f32 %0, %1;" : "=r"(u) : "f"(x));
    return __uint_as_float(u);
}

__device__ __forceinline__ void mma_tf32(float c[4], const unsigned a[4], const unsigned b[2]) {
    asm volatile(
        "mma.sync.aligned.m16n8k8.row.col.f32.tf32.tf32.f32 "
        "{%0,%1,%2,%3}, {%4,%5,%6,%7}, {%8,%9}, {%0,%1,%2,%3};\n"
        : "+f"(c[0]), "+f"(c[1]), "+f"(c[2]), "+f"(c[3])
        : "r"(a[0]), "r"(a[1]), "r"(a[2]), "r"(a[3]), "r"(b[0]), "r"(b[1]));
}

// ---------------------------------------------------------------------------
// TF32 GEMM: C[M,N] = A[M,K] @ W[K,N] + bias[N]
// Block 128x128x32, 8 warps (2x4), warp tile 64x32, mma m16n8k8.
// ---------------------------------------------------------------------------
#define BM 128
#define BN 128
#define BK 32
#define APITCH 36    /* bank = 4*(lane>>2) + (lane&3) = lane : conflict-free frags */
#define BPITCH 132   /* bank = 4*(lane&3) + (lane>>2)        : conflict-free frags */

__global__ __launch_bounds__(256, 1) void gemm_tf32_kernel(
    const float* __restrict__ A, const float* __restrict__ W,
    const float* __restrict__ bias, float* __restrict__ C,
    int M, int N, int K)
{
    __shared__ float As[BM * APITCH];   // [m][k]
    __shared__ float Bs[BK * BPITCH];   // [k][n]

    const int tid  = threadIdx.x;
    const int lane = tid & 31;
    const int warp = tid >> 5;
    const int wr   = warp >> 2;          // 0..1
    const int wc   = warp & 3;           // 0..3
    const int grp  = lane >> 2;          // 0..7
    const int qid  = lane & 3;           // 0..3

    const int m0 = blockIdx.y * BM;
    const int n0 = blockIdx.x * BN;

    const int arow = tid >> 3;           // 0..31 (rows arow + 32*i)
    const int akc  = (tid & 7) * 4;      // k offset within BK
    const int brow = tid >> 5;           // 0..7  (rows brow + 8*i)
    const int bnc  = (tid & 31) * 4;     // n offset within BN

    float acc[4][4][4];
#pragma unroll
    for (int mi = 0; mi < 4; ++mi)
#pragma unroll
        for (int nj = 0; nj < 4; ++nj)
#pragma unroll
            for (int r = 0; r < 4; ++r) acc[mi][nj][r] = 0.f;

    float4 pa[4], pb[4];
#pragma unroll
    for (int i = 0; i < 4; ++i)
        pa[i] = *(const float4*)(A + (size_t)(m0 + arow + 32 * i) * K + akc);
#pragma unroll
    for (int i = 0; i < 4; ++i)
        pb[i] = *(const float4*)(W + (size_t)(brow + 8 * i) * N + n0 + bnc);

    for (int k0 = 0; k0 < K; k0 += BK) {
        // stash current tiles (tf32-rounded)
#pragma unroll
        for (int i = 0; i < 4; ++i) {
            float4 v = pa[i];
            float4 sv = make_float4(tf32r(v.x), tf32r(v.y), tf32r(v.z), tf32r(v.w));
            *(float4*)&As[(arow + 32 * i) * APITCH + akc] = sv;
        }
#pragma unroll
        for (int i = 0; i < 4; ++i) {
            float4 v = pb[i];
            float4 sv = make_float4(tf32r(v.x), tf32r(v.y), tf32r(v.z), tf32r(v.w));
            *(float4*)&Bs[(brow + 8 * i) * BPITCH + bnc] = sv;
        }
        __syncthreads();

        // prefetch next K-chunk
        if (k0 + BK < K) {
            const int kn = k0 + BK;
#pragma unroll
            for (int i = 0; i < 4; ++i)
                pa[i] = *(const float4*)(A + (size_t)(m0 + arow + 32 * i) * K + kn + akc);
#pragma unroll
            for (int i = 0; i < 4; ++i)
                pb[i] = *(const float4*)(W + (size_t)(kn + brow + 8 * i) * N + n0 + bnc);
        }

        // compute 4 k-steps of 8
#pragma unroll
        for (int ks = 0; ks < 4; ++ks) {
            unsigned af[4][4], bf[4][2];
#pragma unroll
            for (int mi = 0; mi < 4; ++mi) {
                const float* base = &As[(wr * 64 + mi * 16 + grp) * APITCH + ks * 8 + qid];
                af[mi][0] = __float_as_uint(base[0]);
                af[mi][1] = __float_as_uint(base[8 * APITCH]);
                af[mi][2] = __float_as_uint(base[4]);
                af[mi][3] = __float_as_uint(base[8 * APITCH + 4]);
            }
#pragma unroll
            for (int nj = 0; nj < 4; ++nj) {
                const float* base = &Bs[(ks * 8 + qid) * BPITCH + wc * 32 + nj * 8 + grp];
                bf[nj][0] = __float_as_uint(base[0]);
                bf[nj][1] = __float_as_uint(base[4 * BPITCH]);
            }
#pragma unroll
            for (int mi = 0; mi < 4; ++mi)
#pragma unroll
                for (int nj = 0; nj < 4; ++nj)
                    mma_tf32(acc[mi][nj], af[mi], bf[nj]);
        }
        __syncthreads();
    }

    // epilogue: bias + store (C layout: c0 (r,2q), c1 (r,2q+1), c2/c3 at r+8)
#pragma unroll
    for (int mi = 0; mi < 4; ++mi) {
#pragma unroll
        for (int nj = 0; nj < 4; ++nj) {
            const int row = m0 + wr * 64 + mi * 16 + grp;
            const int col = n0 + wc * 32 + nj * 8 + 2 * qid;
            const float b0 = bias[col];
            const float b1 = bias[col + 1];
            float2 v0 = make_float2(acc[mi][nj][0] + b0, acc[mi][nj][1] + b1);
            float2 v1 = make_float2(acc[mi][nj][2] + b0, acc[mi][nj][3] + b1);
            *(float2*)&C[(size_t)row * N + col] = v0;
            *(float2*)&C[(size_t)(row + 8) * N + col] = v1;
        }
    }
}

// ---------------------------------------------------------------------------
// Flash attention (causal), tf32 tensor-core.
// Grid: (S/64, B*H), 128 threads (4 warps), 64-query tile, 16 q per warp.
// ---------------------------------------------------------------------------
#define QP 68   /* pitch for Qs/Ks/Ps: A/B-frag conflict-free (68%32==4) */
#define VP 72   /* pitch for Vs: B-frag with qid-major rows (72%32==8)   */

__global__ __launch_bounds__(128) void flash_tf32_kernel(
    const float* __restrict__ qkv, float* __restrict__ out)
{
    extern __shared__ float smf[];
    float* Qs = smf;               // 64*68
    float* Ks = Qs + 64 * QP;      // 64*68
    float* Ps = Ks + 64 * QP;      // 64*68
    float* Vs = Ps + 64 * QP;      // 64*72

    const int tid  = threadIdx.x;
    const int lane = tid & 31;
    const int warp = tid >> 5;     // 0..3, 16 queries each
    const int grp  = lane >> 2;
    const int qid  = lane & 3;

    const int bh = blockIdx.y;
    const int b  = bh / HEADS;
    const int h  = bh % HEADS;
    const int qt = gridDim.x - 1 - blockIdx.x;   // heavy tiles first
    const int q0 = qt * 64;
    const float scale = 0.125f;

    const float* qbase = qkv + (size_t)(b * SEQ) * NQKV + h * HDIM;
    const float* kbase = qbase + DIM;
    const float* vbase = qbase + 2 * DIM;

    // Load Q tile (tf32-rounded)
    {
        const int r = tid >> 4;
        const int c = (tid & 15) * 4;
#pragma unroll
        for (int i = 0; i < 8; ++i) {
            float4 v = *(const float4*)(qbase + (size_t)(q0 + r + 8 * i) * NQKV + c);
            float4 sv = make_float4(tf32r(v.x), tf32r(v.y), tf32r(v.z), tf32r(v.w));
            *(float4*)&Qs[(r + 8 * i) * QP + c] = sv;
        }
    }
    __syncthreads();

    // Q fragments, register-resident for whole kernel
    unsigned qf[8][4];
#pragma unroll
    for (int ks = 0; ks < 8; ++ks) {
        const float* base = &Qs[(warp * 16 + grp) * QP + ks * 8 + qid];
        qf[ks][0] = __float_as_uint(base[0]);
        qf[ks][1] = __float_as_uint(base[8 * QP]);
        qf[ks][2] = __float_as_uint(base[4]);
        qf[ks][3] = __float_as_uint(base[8 * QP + 4]);
    }

    float m0r = -INFINITY, m1r = -INFINITY, l0 = 0.f, l1 = 0.f;
    float o[8][4];
#pragma unroll
    for (int j = 0; j < 8; ++j)
#pragma unroll
        for (int r = 0; r < 4; ++r) o[j][r] = 0.f;

    const int ntiles = qt + 1;
    for (int t = 0; t < ntiles; ++t) {
        const int k0 = t * 64;
        __syncthreads();
        // Load K,V tiles (tf32-rounded)
        {
            const int r = tid >> 4;
            const int c = (tid & 15) * 4;
#pragma unroll
            for (int i = 0; i < 8; ++i) {
                const int row = r + 8 * i;
                float4 kv = *(const float4*)(kbase + (size_t)(k0 + row) * NQKV + c);
                float4 vv = *(const float4*)(vbase + (size_t)(k0 + row) * NQKV + c);
                *(float4*)&Ks[row * QP + c] =
                    make_float4(tf32r(kv.x), tf32r(kv.y), tf32r(kv.z), tf32r(kv.w));
                *(float4*)&Vs[row * VP + c] =
                    make_float4(tf32r(vv.x), tf32r(vv.y), tf32r(vv.z), tf32r(vv.w));
            }
        }
        __syncthreads();

        // S = Q K^T  (warp tile 16x64)
        float s[8][4];
#pragma unroll
        for (int j = 0; j < 8; ++j) {
            s[j][0] = s[j][1] = s[j][2] = s[j][3] = 0.f;
#pragma unroll
            for (int ks = 0; ks < 8; ++ks) {
                const float* base = &Ks[(j * 8 + grp) * QP + ks * 8 + qid];
                unsigned bf[2];
                bf[0] = __float_as_uint(base[0]);
                bf[1] = __float_as_uint(base[4]);
                mma_tf32(s[j], qf[ks], bf);
            }
        }

        // scale + causal mask (diag tile only)
        const bool diag = (t == ntiles - 1);
        const int qi0 = q0 + warp * 16 + grp;
#pragma unroll
        for (int j = 0; j < 8; ++j) {
#pragma unroll
            for (int r = 0; r < 4; ++r) {
                float v = s[j][r] * scale;
                if (diag) {
                    const int kj = k0 + j * 8 + 2 * qid + (r & 1);
                    const int qi = qi0 + ((r >= 2) ? 8 : 0);
                    if (kj > qi) v = -INFINITY;
                }
                s[j][r] = v;
            }
        }

        // online softmax (rows r and r+8; 4-lane groups share a row)
        float mx0 = -INFINITY, mx1 = -INFINITY;
#pragma unroll
        for (int j = 0; j < 8; ++j) {
            mx0 = fmaxf(mx0, fmaxf(s[j][0], s[j][1]));
            mx1 = fmaxf(mx1, fmaxf(s[j][2], s[j][3]));
        }
        mx0 = fmaxf(mx0, __shfl_xor_sync(0xffffffffu, mx0, 1));
        mx0 = fmaxf(mx0, __shfl_xor_sync(0xffffffffu, mx0, 2));
        mx1 = fmaxf(mx1, __shfl_xor_sync(0xffffffffu, mx1, 1));
        mx1 = fmaxf(mx1, __shfl_xor_sync(0xffffffffu, mx1, 2));

        const float nm0 = fmaxf(m0r, mx0);
        const float nm1 = fmaxf(m1r, mx1);
        const float corr0 = __expf(m0r - nm0);
        const float corr1 = __expf(m1r - nm1);
        m0r = nm0; m1r = nm1;

        float sum0 = 0.f, sum1 = 0.f;
#pragma unroll
        for (int j = 0; j < 8; ++j) {
            s[j][0] = __expf(s[j][0] - nm0);
            s[j][1] = __expf(s[j][1] - nm0);
            s[j][2] = __expf(s[j][2] - nm1);
            s[j][3] = __expf(s[j][3] - nm1);
            sum0 += s[j][0] + s[j][1];
            sum1 += s[j][2] + s[j][3];
        }
        sum0 += __shfl_xor_sync(0xffffffffu, sum0, 1);
        sum0 += __shfl_xor_sync(0xffffffffu, sum0, 2);
        sum1 += __shfl_xor_sync(0xffffffffu, sum1, 1);
        sum1 += __shfl_xor_sync(0xffffffffu, sum1, 2);
        l0 = l0 * corr0 + sum0;
        l1 = l1 * corr1 + sum1;
#pragma unroll
        for (int j = 0; j < 8; ++j) {
            o[j][0] *= corr0; o[j][1] *= corr0;
            o[j][2] *= corr1; o[j][3] *= corr1;
        }

        // P fragments -> smem (C-layout -> A-layout round trip), warp-private
#pragma unroll
        for (int j = 0; j < 8; ++j) {
            float* p0 = &Ps[(warp * 16 + grp) * QP + j * 8 + 2 * qid];
            float* p1 = &Ps[(warp * 16 + grp + 8) * QP + j * 8 + 2 * qid];
            *(float2*)p0 = make_float2(tf32r(s[j][0]), tf32r(s[j][1]));
            *(float2*)p1 = make_float2(tf32r(s[j][2]), tf32r(s[j][3]));
        }
        __syncwarp();

        // O += P @ V
#pragma unroll
        for (int ks = 0; ks < 8; ++ks) {
            const float* abase = &Ps[(warp * 16 + grp) * QP + ks * 8 + qid];
            unsigned pf[4];
            pf[0] = __float_as_uint(abase[0]);
            pf[1] = __float_as_uint(abase[8 * QP]);
            pf[2] = __float_as_uint(abase[4]);
            pf[3] = __float_as_uint(abase[8 * QP + 4]);
#pragma unroll
            for (int j = 0; j < 8; ++j) {
                const float* bbase = &Vs[(ks * 8 + qid) * VP + j * 8 + grp];
                unsigned bf[2];
                bf[0] = __float_as_uint(bbase[0]);
                bf[1] = __float_as_uint(bbase[4 * VP]);
                mma_tf32(o[j], pf, bf);
            }
        }
    }

    // write normalized output
    const float inv0 = 1.0f / l0;
    const float inv1 = 1.0f / l1;
    const int row0 = q0 + warp * 16 + grp;
#pragma unroll
    for (int j = 0; j < 8; ++j) {
        const int col = h * HDIM + j * 8 + 2 * qid;
        *(float2*)&out[((size_t)(b * SEQ) + row0) * DIM + col] =
            make_float2(o[j][0] * inv0, o[j][1] * inv0);
        *(float2*)&out[((size_t)(b * SEQ) + row0 + 8) * DIM + col] =
            make_float2(o[j][2] * inv1, o[j][3] * inv1);
    }
}

// ---------------------------------------------------------------------------
extern "C" void kernel_launch(void* const* d_in, const int* in_sizes, int n_in,
                              void* d_out, int out_size)
{
    const float* x      = (const float*)d_in[0];   // [B,S,D]
    const float* qkv_w  = (const float*)d_in[1];   // [D, 3D]
    const float* qkv_b  = (const float*)d_in[2];   // [3D]
    const float* out_w  = (const float*)d_in[3];   // [D, D]
    const float* out_b  = (const float*)d_in[4];   // [D]
    float* out = (float*)d_out;

    float* qkv_buf = nullptr;
    float* att_buf = nullptr;
    cudaGetSymbolAddress((void**)&qkv_buf, g_qkv);
    cudaGetSymbolAddress((void**)&att_buf, g_att);

    const int flash_smem = (3 * 64 * QP + 64 * VP) * (int)sizeof(float);  // 70656
    cudaFuncSetAttribute(flash_tf32_kernel,
                         cudaFuncAttributeMaxDynamicSharedMemorySize, flash_smem);

    // 1) QKV projection: [4096,1024] @ [1024,3072] + b
    {
        dim3 grid(NQKV / BN, MROWS / BM);
        gemm_tf32_kernel<<<grid, 256>>>(x, qkv_w, qkv_b, qkv_buf,
                                        MROWS, NQKV, DIM);
    }
    // 2) Causal flash attention (tf32 tensor cores)
    {
        dim3 grid(SEQ / 64, BATCH * HEADS);
        flash_tf32_kernel<<<grid, 128, flash_smem>>>(qkv_buf, att_buf);
    }
    // 3) Output projection: [4096,1024] @ [1024,1024] + b
    {
        dim3 grid(DIM / BN, MROWS / BM);
        gemm_tf32_kernel<<<grid, 256>>>(att_buf, out_w, out_b, out,
                                        MROWS, DIM, DIM);
    }
}